// round 16
// baseline (speedup 1.0000x reference)
#include <cuda_runtime.h>
#include <cuda_fp16.h>
#include <cstdint>
#include <float.h>

// Problem constants
#define B_ 8
#define S_ 2048
#define D_ 512
#define Q_ 8
#define C_ 1024
#define T_ (B_*S_)            // 16384 tokens

#define TM 64                 // tokens per CTA (4 m-tiles of 16)
#define NCTA (T_/TM)          // 256
#define NTHREADS 256          // 8 warps = 2 m-halves x 4 n-quarters
#define NKS 32                // 512/16 k-steps
#define TOTH (Q_*128)         // 1024 half-chunks (8KB each)
#define TAU 0.25f

// smem byte offsets (~105.6KB -> 2 CTAs/SM)
#define OFF_AHI  0            // [4 mt][32 ks][32 lane][16B] = 64KB
#define OFF_B    65536        // 4-slot ring x 8KB = 32KB
#define OFF_T3   98304        // [4 nq][4 mt][16 row][6 u32] = 6144B
#define OFF_IDX  104448       // 64 int
#define OFF_NF   104704
#define OFF_NP   104708
#define OFF_FLAG 104712       // 64 int
#define OFF_PM   104968       // 64 int
#define OFF_PC   105224       // 64 int
#define OFF_RB   105480       // 8 f32
#define OFF_RI   105512       // 8 int
#define OFF_LOSS 105544       // 8 f32
#define SMEM_BYTES 105600

__device__ float  g_res[(size_t)T_*D_];             // 32MB residual
__device__ uint4  g_bfrag2[(size_t)Q_*64*NKS*32];   // 8MB paired fp16-hi frags
__device__ float  g_cnorm[Q_*C_];
__device__ float  g_part[NCTA*Q_];

// ---------------------------------------------------------------------------
__device__ __forceinline__ void cp_async16(unsigned sdst, const void* gsrc) {
    asm volatile("cp.async.cg.shared.global [%0], [%1], 16;" :: "r"(sdst), "l"(gsrc));
}
#define CP_COMMIT() asm volatile("cp.async.commit_group;" ::: "memory")
#define CP_WAIT2()  asm volatile("cp.async.wait_group 2;" ::: "memory")
__device__ __forceinline__ unsigned smem_u32(const void* p) {
    unsigned a;
    asm("{ .reg .u64 t; cvta.to.shared.u64 t, %1; cvt.u32.u64 %0, t; }"
        : "=r"(a) : "l"(p));
    return a;
}
__device__ __forceinline__ void mma_f16(float* c, unsigned a0, unsigned a1,
                                        unsigned a2, unsigned a3,
                                        unsigned b0, unsigned b1) {
    asm("mma.sync.aligned.m16n8k16.row.col.f32.f16.f16.f32 "
        "{%0,%1,%2,%3},{%4,%5,%6,%7},{%8,%9},{%0,%1,%2,%3};"
        : "+f"(c[0]), "+f"(c[1]), "+f"(c[2]), "+f"(c[3])
        : "r"(a0), "r"(a1), "r"(a2), "r"(a3), "r"(b0), "r"(b1));
}
__device__ __forceinline__ unsigned pack_hi(float x0, float x1) {
    __half h0 = __float2half_rn(x0);
    __half h1 = __float2half_rn(x1);
    return (unsigned)__half_as_ushort(h0) | ((unsigned)__half_as_ushort(h1) << 16);
}

struct Top3 { float s0, s1, s2; int i0, i1, i2; };
__device__ __forceinline__ void t3_init(Top3& t) {
    t.s0 = t.s1 = t.s2 = FLT_MAX; t.i0 = t.i1 = t.i2 = 0x7fffffff;
}
__device__ __forceinline__ void t3_ins(Top3& t, float s, int i) {
    if (s < t.s2 || (s == t.s2 && i < t.i2)) {
        if (s < t.s1 || (s == t.s1 && i < t.i1)) {
            t.s2 = t.s1; t.i2 = t.i1;
            if (s < t.s0 || (s == t.s0 && i < t.i0)) {
                t.s1 = t.s0; t.i1 = t.i0; t.s0 = s; t.i0 = i;
            } else { t.s1 = s; t.i1 = i; }
        } else { t.s2 = s; t.i2 = i; }
    }
}
__device__ __forceinline__ void t3_shxor(Top3& t, int m) {
    float s0 = __shfl_xor_sync(0xffffffffu, t.s0, m);
    float s1 = __shfl_xor_sync(0xffffffffu, t.s1, m);
    float s2 = __shfl_xor_sync(0xffffffffu, t.s2, m);
    int   i0 = __shfl_xor_sync(0xffffffffu, t.i0, m);
    int   i1 = __shfl_xor_sync(0xffffffffu, t.i1, m);
    int   i2 = __shfl_xor_sync(0xffffffffu, t.i2, m);
    t3_ins(t, s0, i0); t3_ins(t, s1, i1); t3_ins(t, s2, i2);
}

// ---------------------------------------------------------------------------
// Prep: code norms
__global__ void rvq_prep_norm(const float* __restrict__ cbs) {
    int r = blockIdx.x*blockDim.x + threadIdx.x;
    if (r < Q_*C_) {
        const float4* p = (const float4*)(cbs + (size_t)r*D_);
        float s = 0.f;
        #pragma unroll 8
        for (int i = 0; i < D_/4; i++) {
            float4 v = p[i];
            s = fmaf(v.x, v.x, s); s = fmaf(v.y, v.y, s);
            s = fmaf(v.z, v.z, s); s = fmaf(v.w, v.w, s);
        }
        g_cnorm[r] = s;
    }
}

// Prep: paired fp16-hi B fragments: [q][npair 64][ks 32][lane 32] uint4
// pair p covers codes p*16+row and p*16+8+row (row = lane>>2)
__global__ void rvq_prep_bfrag2(const float* __restrict__ cbs) {
    int t = blockIdx.x*blockDim.x + threadIdx.x;
    if (t >= Q_*64*NKS*32) return;
    int lane  = t & 31;
    int ks    = (t >> 5) & 31;
    int npair = (t >> 10) & 63;
    int q     = t >> 16;
    int code0 = npair*16 + (lane >> 2);
    int code1 = code0 + 8;
    int k0    = ks*16 + (lane & 3)*2;
    const float* c0 = cbs + ((size_t)q*C_ + code0)*D_;
    const float* c1 = cbs + ((size_t)q*C_ + code1)*D_;
    float2 a0 = *(const float2*)(c0 + k0);
    float2 a1 = *(const float2*)(c0 + k0 + 8);
    float2 b0 = *(const float2*)(c1 + k0);
    float2 b1 = *(const float2*)(c1 + k0 + 8);
    g_bfrag2[t] = make_uint4(pack_hi(a0.x, a0.y), pack_hi(a1.x, a1.y),
                             pack_hi(b0.x, b0.y), pack_hi(b1.x, b1.y));
}

// ---------------------------------------------------------------------------
// stage half-chunk hidx into an 8KB ring slot.
// hidx: q = hidx>>7; rem = hidx&127; ng = rem>>4; hc = rem&15; ks = hc*2+{0,1}
// slot layout [nq 4][prl 2][ksl2 2][lane 32] x uint4; npair = nq*16 + ng*2 + prl
// ---------------------------------------------------------------------------
__device__ __forceinline__ void stage_half(int hidx, unsigned sdst, int tid) {
    int q  = hidx >> 7;
    int rem = hidx & 127;
    int ng = rem >> 4;
    int hc = rem & 15;
    #pragma unroll
    for (int j = 0; j < 2; j++) {
        int c    = tid + j*NTHREADS;       // 0..511 uint4 units
        int nqs  = c >> 7;
        int prl  = (c >> 6) & 1;
        int ksl2 = (c >> 5) & 1;
        int ln   = c & 31;
        int npair = nqs*16 + ng*2 + prl;
        int ks    = hc*2 + ksl2;
        const uint4* src = g_bfrag2 +
            ((((size_t)q*64 + npair)*NKS + ks)*32 + ln);
        cp_async16(sdst + (c << 4), src);
    }
}

// ---------------------------------------------------------------------------
__global__ __launch_bounds__(NTHREADS, 2)
void rvq_main(const float* __restrict__ x, const float* __restrict__ cbs,
              float* __restrict__ out, int out_size) {
    extern __shared__ char smem[];
    const unsigned sb = smem_u32(smem);
    float* s_t3   = (float*)(smem + OFF_T3);
    int*   s_idx  = (int*)(smem + OFF_IDX);
    int*   s_nf   = (int*)(smem + OFF_NF);
    int*   s_np   = (int*)(smem + OFF_NP);
    int*   s_flag = (int*)(smem + OFF_FLAG);
    int*   s_pm   = (int*)(smem + OFF_PM);
    int*   s_pc   = (int*)(smem + OFF_PC);
    float* s_rb   = (float*)(smem + OFF_RB);
    int*   s_ri   = (int*)(smem + OFF_RI);
    float* s_loss = (float*)(smem + OFF_LOSS);

    const int tid  = threadIdx.x;
    const int wid  = tid >> 5;
    const int lane = tid & 31;
    const int mh   = wid & 1;        // m-half: m-tiles mh*2, mh*2+1
    const int nq   = wid >> 1;       // n-quarter: codes nq*256..+255
    const int mt0  = mh*2, mt1 = mh*2 + 1;
    const size_t tok0 = (size_t)blockIdx.x * TM;

    // prime 3 ring slots
    stage_half(0, sb + OFF_B + 0*8192, tid); CP_COMMIT();
    stage_half(1, sb + OFF_B + 1*8192, tid); CP_COMMIT();
    stage_half(2, sb + OFF_B + 2*8192, tid); CP_COMMIT();

    int hcnt = 0;   // global half-chunk counter

    for (int q = 0; q < Q_; q++) {
        const float* rsrc = q ? (const float*)g_res : x;
        const float* cbq  = cbs + (size_t)q*C_*D_;
        const float* cnq  = g_cnorm + q*C_;

        // ---- stage A fragments (fp16 hi) ----
        for (int s = 0; s < 16; s++) {
            int slot = tid + s*NTHREADS;           // (mt,ks,lane)
            int smt = slot >> 10, sks = (slot >> 5) & 31, sls = slot & 31;
            int rowa = smt*16 + (sls >> 2);
            int k0 = sks*16 + (sls & 3)*2;
            const float* rp = rsrc + (tok0 + rowa)*D_ + k0;
            float2 v0 = *(const float2*)(rp);
            float2 v1 = *(const float2*)(rp + 8*D_);
            float2 v2 = *(const float2*)(rp + 8);
            float2 v3 = *(const float2*)(rp + 8*D_ + 8);
            *(uint4*)(smem + OFF_AHI + slot*16) =
                make_uint4(pack_hi(v0.x, v0.y), pack_hi(v1.x, v1.y),
                           pack_hi(v2.x, v2.y), pack_hi(v3.x, v3.y));
        }
        if (tid == 0) { *s_nf = 0; *s_np = 0; }
        __syncthreads();

        Top3 t3[2][2];   // [mi][nt-row-group]
        t3_init(t3[0][0]); t3_init(t3[0][1]);
        t3_init(t3[1][0]); t3_init(t3[1][1]);

        for (int ng = 0; ng < 8; ng++) {
            float acc[2][2][2][4];   // [mi][prl][nt][4]
            #pragma unroll
            for (int mi = 0; mi < 2; mi++)
                #pragma unroll
                for (int p2 = 0; p2 < 2; p2++)
                    #pragma unroll
                    for (int nt = 0; nt < 2; nt++)
                        #pragma unroll
                        for (int j = 0; j < 4; j++) acc[mi][p2][nt][j] = 0.f;

            for (int hc = 0; hc < 16; hc++) {
                CP_WAIT2();            // half-chunk hcnt resident
                __syncthreads();       // visibility + safe slot overwrite
                if (hcnt + 3 < TOTH)
                    stage_half(hcnt+3, sb + OFF_B + ((hcnt+3)&3)*8192, tid);
                CP_COMMIT();           // uniform group count (may be empty)

                const char* bbase = smem + OFF_B + (hcnt&3)*8192 + nq*2048;
                #pragma unroll
                for (int ksl = 0; ksl < 2; ksl++) {
                    int ks = hc*2 + ksl;
                    uint4 A0 = *(const uint4*)(smem + OFF_AHI +
                                (unsigned)(((mt0*32 + ks)*32 + lane)*16));
                    uint4 A1 = *(const uint4*)(smem + OFF_AHI +
                                (unsigned)(((mt1*32 + ks)*32 + lane)*16));
                    #pragma unroll
                    for (int prl = 0; prl < 2; prl++) {
                        uint4 Bv = *(const uint4*)(bbase + prl*1024 + ksl*512 + lane*16);
                        mma_f16(acc[0][prl][0], A0.x, A0.y, A0.z, A0.w, Bv.x, Bv.y);
                        mma_f16(acc[0][prl][1], A0.x, A0.y, A0.z, A0.w, Bv.z, Bv.w);
                        mma_f16(acc[1][prl][0], A1.x, A1.y, A1.z, A1.w, Bv.x, Bv.y);
                        mma_f16(acc[1][prl][1], A1.x, A1.y, A1.z, A1.w, Bv.z, Bv.w);
                    }
                }
                hcnt++;
            }

            // epilogue: scores for this warp's 32 codes of group ng
            #pragma unroll
            for (int prl = 0; prl < 2; prl++) {
                #pragma unroll
                for (int nt = 0; nt < 2; nt++) {
                    int n0 = nq*256 + ng*32 + prl*16 + nt*8 + (lane & 3)*2;
                    float cn0 = __ldg(cnq + n0), cn1 = __ldg(cnq + n0 + 1);
                    #pragma unroll
                    for (int mi = 0; mi < 2; mi++) {
                        // c0,c1 -> row group (lane>>2); c2,c3 -> row+8
                        t3_ins(t3[mi][0], fmaf(-2.f, acc[mi][prl][nt][0], cn0), n0);
                        t3_ins(t3[mi][0], fmaf(-2.f, acc[mi][prl][nt][1], cn1), n0+1);
                        t3_ins(t3[mi][1], fmaf(-2.f, acc[mi][prl][nt][2], cn0), n0);
                        t3_ins(t3[mi][1], fmaf(-2.f, acc[mi][prl][nt][3], cn1), n0+1);
                    }
                }
            }
        }

        // quad merge + publish (4 lanes share each C row)
        #pragma unroll
        for (int mi = 0; mi < 2; mi++) {
            t3_shxor(t3[mi][0], 1); t3_shxor(t3[mi][0], 2);
            t3_shxor(t3[mi][1], 1); t3_shxor(t3[mi][1], 2);
            if ((lane & 3) == 0) {
                int r = lane >> 2;
                int mtg = mh*2 + mi;
                float* e = s_t3 + ((nq*4 + mtg)*16 + r)*6;
                e[0] = t3[mi][0].s0; e[1] = t3[mi][0].s1; e[2] = t3[mi][0].s2;
                ((int*)e)[3] = t3[mi][0].i0; ((int*)e)[4] = t3[mi][0].i1;
                ((int*)e)[5] = t3[mi][0].i2;
                float* f = s_t3 + ((nq*4 + mtg)*16 + r + 8)*6;
                f[0] = t3[mi][1].s0; f[1] = t3[mi][1].s1; f[2] = t3[mi][1].s2;
                ((int*)f)[3] = t3[mi][1].i0; ((int*)f)[4] = t3[mi][1].i1;
                ((int*)f)[5] = t3[mi][1].i2;
            }
        }
        __syncthreads();

        // merge quarters + decide (warps nq==0: wid 0,1; 32 tokens each)
        if (nq == 0) {
            int mtg = mh*2 + (lane >> 4);
            int r   = lane & 15;
            Top3 t; t3_init(t);
            #pragma unroll
            for (int k = 0; k < 4; k++) {
                const float* e = s_t3 + ((k*4 + mtg)*16 + r)*6;
                t3_ins(t, e[0], ((const int*)e)[3]);
                t3_ins(t, e[1], ((const int*)e)[4]);
                t3_ins(t, e[2], ((const int*)e)[5]);
            }
            int token = mtg*16 + r;
            s_idx[token] = t.i0;
            if (t.s2 - t.s0 < TAU) {
                int p = atomicAdd(s_nf, 1);
                s_flag[p] = token;
            } else if (t.s1 - t.s0 < TAU) {
                int p = atomicAdd(s_np, 1);
                s_pm[p] = token; s_pc[p] = t.i1;
            }
        }
        __syncthreads();

        // ---- pair rescore: exact fp32 compare of top-2 (one warp each) ----
        int np = *s_np;
        for (int p = wid; p < np; p += 8) {
            int m = s_pm[p];
            int ca = s_idx[m], cb2 = s_pc[p];
            const float* rr = rsrc + (tok0 + m)*D_;
            const float* pa = cbq + (size_t)ca*D_;
            const float* pb = cbq + (size_t)cb2*D_;
            float da = 0.f, db = 0.f;
            #pragma unroll
            for (int k = 0; k < 16; k++) {
                float rv = rr[lane*16 + k];
                da = fmaf(rv, pa[lane*16 + k], da);
                db = fmaf(rv, pb[lane*16 + k], db);
            }
            #pragma unroll
            for (int off = 16; off > 0; off >>= 1) {
                da += __shfl_down_sync(0xffffffffu, da, off);
                db += __shfl_down_sync(0xffffffffu, db, off);
            }
            if (lane == 0) {
                float sa = fmaf(-2.f, da, __ldg(cnq + ca));
                float sc = fmaf(-2.f, db, __ldg(cnq + cb2));
                int win = (sc < sa || (sc == sa && cb2 < ca)) ? cb2 : ca;
                s_idx[m] = win;
            }
        }
        __syncthreads();

        // ---- full exact rescore (rare) ----
        int nf = *s_nf;
        for (int f = 0; f < nf; f++) {
            int m = s_flag[f];
            const float* rr = rsrc + (tok0 + m)*D_;
            float lb = FLT_MAX; int li = 0x7fffffff;
            #pragma unroll 1
            for (int jj = 0; jj < 4; jj++) {
                int code = wid*128 + jj*32 + lane;
                const float* cr = cbq + (size_t)code*D_;
                float dot = 0.f;
                #pragma unroll 8
                for (int d = 0; d < D_; d++) dot = fmaf(rr[d], cr[d], dot);
                float sc = fmaf(-2.f, dot, __ldg(cnq + code));
                if (sc < lb || (sc == lb && code < li)) { lb = sc; li = code; }
            }
            #pragma unroll
            for (int off = 16; off > 0; off >>= 1) {
                float os = __shfl_down_sync(0xffffffffu, lb, off);
                int   oi = __shfl_down_sync(0xffffffffu, li, off);
                if (os < lb || (os == lb && oi < li)) { lb = os; li = oi; }
            }
            if (lane == 0) { s_rb[wid] = lb; s_ri[wid] = li; }
            __syncthreads();
            if (tid == 0) {
                float fb = FLT_MAX; int fi = 0x7fffffff;
                #pragma unroll
                for (int wv = 0; wv < 8; wv++)
                    if (s_rb[wv] < fb || (s_rb[wv] == fb && s_ri[wv] < fi)) {
                        fb = s_rb[wv]; fi = s_ri[wv];
                    }
                s_idx[m] = fi;
            }
            __syncthreads();
        }

        // ---- residual update + loss + index output ----
        float lloss = 0.f;
        #pragma unroll 1
        for (int i = 0; i < 8; i++) {
            int m = wid*8 + i;
            int idx = s_idx[m];
            const float* cr = cbq + (size_t)idx*D_;
            const float* rr = rsrc + (tok0 + m)*D_;
            float* wr = g_res + (tok0 + m)*D_;
            #pragma unroll
            for (int it = 0; it < 4; it++) {
                int d = it*128 + lane*4;
                float4 rv = *(const float4*)(rr + d);
                float4 cv = *(const float4*)(cr + d);
                float4 nv = make_float4(rv.x-cv.x, rv.y-cv.y, rv.z-cv.z, rv.w-cv.w);
                *(float4*)(wr + d) = nv;
                lloss = fmaf(nv.x, nv.x, lloss);
                lloss = fmaf(nv.y, nv.y, lloss);
                lloss = fmaf(nv.z, nv.z, lloss);
                lloss = fmaf(nv.w, nv.w, lloss);
            }
            if (lane == 0 && out_size >= (int)((long long)T_*D_ + (long long)T_*Q_))
                out[(size_t)T_*D_ + (tok0 + m)*Q_ + q] = (float)idx;
        }
        #pragma unroll
        for (int off = 16; off > 0; off >>= 1)
            lloss += __shfl_down_sync(0xffffffffu, lloss, off);
        if (lane == 0) s_loss[wid] = lloss;
        __syncthreads();
        if (tid == 0) {
            float s = 0.f;
            #pragma unroll
            for (int i = 0; i < 8; i++) s += s_loss[i];
            g_part[blockIdx.x*Q_ + q] = s;
        }
        __syncthreads();   // residual visible before next q's staging
    }

    // quantized_out = x - residual_final
    for (int i = tid; i < TM*(D_/4); i += NTHREADS) {
        int row = i >> 7, c4 = i & 127;
        float4 xv = ((const float4*)(x + (tok0+row)*D_))[c4];
        float4 rv = ((const float4*)(g_res + (tok0+row)*D_))[c4];
        ((float4*)(out + (tok0+row)*D_))[c4] =
            make_float4(xv.x-rv.x, xv.y-rv.y, xv.z-rv.z, xv.w-rv.w);
    }
}

// ---------------------------------------------------------------------------
__global__ void rvq_fin(float* __restrict__ out, int out_size) {
    int q = threadIdx.x;
    if (q < Q_ && out_size >= (int)((long long)T_*D_ + (long long)T_*Q_ + Q_)) {
        float s = 0.f;
        for (int c = 0; c < NCTA; c++) s += g_part[c*Q_ + q];
        out[(size_t)T_*D_ + (size_t)T_*Q_ + q] = s / (float)((long long)T_*D_);
    }
}

// ---------------------------------------------------------------------------
extern "C" void kernel_launch(void* const* d_in, const int* in_sizes, int n_in,
                              void* d_out, int out_size) {
    const float* x;
    const float* cbs;
    if (in_sizes[0] == T_*D_) { x = (const float*)d_in[0]; cbs = (const float*)d_in[1]; }
    else                      { x = (const float*)d_in[1]; cbs = (const float*)d_in[0]; }
    float* out = (float*)d_out;

    cudaFuncSetAttribute(rvq_main,
                         cudaFuncAttributeMaxDynamicSharedMemorySize, SMEM_BYTES);

    rvq_prep_norm<<<(Q_*C_ + 255)/256, 256>>>(cbs);
    rvq_prep_bfrag2<<<(Q_*64*NKS*32)/256, 256>>>(cbs);
    rvq_main<<<NCTA, NTHREADS, SMEM_BYTES>>>(x, cbs, out, out_size);
    rvq_fin<<<1, 32>>>(out, out_size);
}

// round 17
// speedup vs baseline: 1.6713x; 1.6713x over previous
#include <cuda_runtime.h>
#include <cuda_fp16.h>
#include <cstdint>
#include <float.h>

// Problem constants
#define B_ 8
#define S_ 2048
#define D_ 512
#define Q_ 8
#define C_ 1024
#define T_ (B_*S_)            // 16384 tokens

#define TM 64                 // tokens per CTA (4 m-tiles of 16)
#define NCTA (T_/TM)          // 256
#define NTHREADS 256          // 8 warps = 4 mt x 2 nh
#define NKS 32                // 512/16 k-steps
#define TOTH (Q_*128)         // 1024 half-chunks (8KB each)
#define TAU 0.25f

// smem byte offsets (~100KB -> 2 CTAs/SM)
#define OFF_AHI  0            // [4 mt][32 ks][32 lane][16B] = 64KB
#define OFF_B    65536        // 4-slot ring x 8KB = 32KB
#define OFF_T3   98304        // [2 nh][4 mt][16 row][6 u32] = 3072B
#define OFF_IDX  101376       // 64 int
#define OFF_NF   101632
#define OFF_NP   101636
#define OFF_FLAG 101640       // 64 int
#define OFF_PM   101896       // 64 int
#define OFF_PC   102152       // 64 int
#define OFF_RB   102408       // 8 f32
#define OFF_RI   102440       // 8 int
#define OFF_LOSS 102472       // 8 f32
#define SMEM_BYTES 102528

__device__ float  g_res[(size_t)T_*D_];             // 32MB residual
__device__ uint4  g_bfrag2[(size_t)Q_*64*NKS*32];   // 8MB paired fp16-hi frags
__device__ float  g_cnorm[Q_*C_];
__device__ float  g_part[NCTA*Q_];

// ---------------------------------------------------------------------------
__device__ __forceinline__ void cp_async16(unsigned sdst, const void* gsrc) {
    asm volatile("cp.async.cg.shared.global [%0], [%1], 16;" :: "r"(sdst), "l"(gsrc));
}
#define CP_COMMIT() asm volatile("cp.async.commit_group;" ::: "memory")
#define CP_WAIT2()  asm volatile("cp.async.wait_group 2;" ::: "memory")
#define BAR_HALF(id) asm volatile("bar.sync %0, 128;" :: "r"(id) : "memory")
__device__ __forceinline__ unsigned smem_u32(const void* p) {
    unsigned a;
    asm("{ .reg .u64 t; cvta.to.shared.u64 t, %1; cvt.u32.u64 %0, t; }"
        : "=r"(a) : "l"(p));
    return a;
}
__device__ __forceinline__ void mma_f16(float* c, unsigned a0, unsigned a1,
                                        unsigned a2, unsigned a3,
                                        unsigned b0, unsigned b1) {
    asm("mma.sync.aligned.m16n8k16.row.col.f32.f16.f16.f32 "
        "{%0,%1,%2,%3},{%4,%5,%6,%7},{%8,%9},{%0,%1,%2,%3};"
        : "+f"(c[0]), "+f"(c[1]), "+f"(c[2]), "+f"(c[3])
        : "r"(a0), "r"(a1), "r"(a2), "r"(a3), "r"(b0), "r"(b1));
}
__device__ __forceinline__ unsigned pack_hi(float x0, float x1) {
    __half h0 = __float2half_rn(x0);
    __half h1 = __float2half_rn(x1);
    return (unsigned)__half_as_ushort(h0) | ((unsigned)__half_as_ushort(h1) << 16);
}

struct Top3 { float s0, s1, s2; int i0, i1, i2; };
__device__ __forceinline__ void t3_init(Top3& t) {
    t.s0 = t.s1 = t.s2 = FLT_MAX; t.i0 = t.i1 = t.i2 = 0x7fffffff;
}
__device__ __forceinline__ void t3_ins(Top3& t, float s, int i) {
    if (s < t.s2 || (s == t.s2 && i < t.i2)) {
        if (s < t.s1 || (s == t.s1 && i < t.i1)) {
            t.s2 = t.s1; t.i2 = t.i1;
            if (s < t.s0 || (s == t.s0 && i < t.i0)) {
                t.s1 = t.s0; t.i1 = t.i0; t.s0 = s; t.i0 = i;
            } else { t.s1 = s; t.i1 = i; }
        } else { t.s2 = s; t.i2 = i; }
    }
}
__device__ __forceinline__ void t3_shxor(Top3& t, int m) {
    float s0 = __shfl_xor_sync(0xffffffffu, t.s0, m);
    float s1 = __shfl_xor_sync(0xffffffffu, t.s1, m);
    float s2 = __shfl_xor_sync(0xffffffffu, t.s2, m);
    int   i0 = __shfl_xor_sync(0xffffffffu, t.i0, m);
    int   i1 = __shfl_xor_sync(0xffffffffu, t.i1, m);
    int   i2 = __shfl_xor_sync(0xffffffffu, t.i2, m);
    t3_ins(t, s0, i0); t3_ins(t, s1, i1); t3_ins(t, s2, i2);
}

// ---------------------------------------------------------------------------
__global__ void rvq_dummy() {}

// Prep: code norms
__global__ void rvq_prep_norm(const float* __restrict__ cbs) {
    int r = blockIdx.x*blockDim.x + threadIdx.x;
    if (r < Q_*C_) {
        const float4* p = (const float4*)(cbs + (size_t)r*D_);
        float s = 0.f;
        #pragma unroll 8
        for (int i = 0; i < D_/4; i++) {
            float4 v = p[i];
            s = fmaf(v.x, v.x, s); s = fmaf(v.y, v.y, s);
            s = fmaf(v.z, v.z, s); s = fmaf(v.w, v.w, s);
        }
        g_cnorm[r] = s;
    }
}

// Prep: paired fp16-hi B fragments: [q][npair 64][ks 32][lane 32] uint4
__global__ void rvq_prep_bfrag2(const float* __restrict__ cbs) {
    int t = blockIdx.x*blockDim.x + threadIdx.x;
    if (t >= Q_*64*NKS*32) return;
    int lane  = t & 31;
    int ks    = (t >> 5) & 31;
    int npair = (t >> 10) & 63;
    int q     = t >> 16;
    int code0 = npair*16 + (lane >> 2);
    int code1 = code0 + 8;
    int k0    = ks*16 + (lane & 3)*2;
    const float* c0 = cbs + ((size_t)q*C_ + code0)*D_;
    const float* c1 = cbs + ((size_t)q*C_ + code1)*D_;
    float2 a0 = *(const float2*)(c0 + k0);
    float2 a1 = *(const float2*)(c0 + k0 + 8);
    float2 b0 = *(const float2*)(c1 + k0);
    float2 b1 = *(const float2*)(c1 + k0 + 8);
    g_bfrag2[t] = make_uint4(pack_hi(a0.x, a0.y), pack_hi(a1.x, a1.y),
                             pack_hi(b0.x, b0.y), pack_hi(b1.x, b1.y));
}

// ---------------------------------------------------------------------------
// stage ONLY half `nh` of half-chunk hidx into its 8KB ring slot.
// hidx: q = hidx>>7; rem = hidx&127; ng = rem>>4; hc = rem&15; ks = hc*2+{0,1}
// slot layout [h 2][pr 4][ksl2 2][lane 32] x uint4; npair = h*32+ng*4+pr.
// gtid = tid & 127 (within the 4-warp group). 256 uint4 per half -> 2 per thread.
// ---------------------------------------------------------------------------
__device__ __forceinline__ void stage_half_h(int hidx, unsigned slotbase,
                                             int gtid, int nh) {
    int q  = hidx >> 7;
    int rem = hidx & 127;
    int ng = rem >> 4;
    int hc = rem & 15;
    #pragma unroll
    for (int j = 0; j < 2; j++) {
        int c    = gtid + j*128;           // 0..255 uint4 units within half
        int pr   = c >> 6;
        int ksl2 = (c >> 5) & 1;
        int ln   = c & 31;
        int npair = nh*32 + ng*4 + pr;
        int ks    = hc*2 + ksl2;
        const uint4* src = g_bfrag2 +
            ((((size_t)q*64 + npair)*NKS + ks)*32 + ln);
        cp_async16(slotbase + (unsigned)(nh*4096) + (unsigned)(c << 4), src);
    }
}

// ---------------------------------------------------------------------------
__global__ __launch_bounds__(NTHREADS, 2)
void rvq_main(const float* __restrict__ x, const float* __restrict__ cbs,
              float* __restrict__ out, int out_size) {
    extern __shared__ char smem[];
    const unsigned sb = smem_u32(smem);
    float* s_t3   = (float*)(smem + OFF_T3);
    int*   s_idx  = (int*)(smem + OFF_IDX);
    int*   s_nf   = (int*)(smem + OFF_NF);
    int*   s_np   = (int*)(smem + OFF_NP);
    int*   s_flag = (int*)(smem + OFF_FLAG);
    int*   s_pm   = (int*)(smem + OFF_PM);
    int*   s_pc   = (int*)(smem + OFF_PC);
    float* s_rb   = (float*)(smem + OFF_RB);
    int*   s_ri   = (int*)(smem + OFF_RI);
    float* s_loss = (float*)(smem + OFF_LOSS);

    const int tid  = threadIdx.x;
    const int wid  = tid >> 5;
    const int lane = tid & 31;
    const int mt   = wid & 3;        // m-tile
    const int nh   = wid >> 2;       // code half == staging group
    const int gtid = tid & 127;      // id within 4-warp group
    const size_t tok0 = (size_t)blockIdx.x * TM;

    // prime 3 ring slots (each group stages its own half)
    stage_half_h(0, sb + OFF_B + 0*8192, gtid, nh); CP_COMMIT();
    stage_half_h(1, sb + OFF_B + 1*8192, gtid, nh); CP_COMMIT();
    stage_half_h(2, sb + OFF_B + 2*8192, gtid, nh); CP_COMMIT();

    int hcnt = 0;   // global half-chunk counter

    for (int q = 0; q < Q_; q++) {
        const float* rsrc = q ? (const float*)g_res : x;
        const float* cbq  = cbs + (size_t)q*C_*D_;
        const float* cnq  = g_cnorm + q*C_;

        // ---- stage A fragments (fp16 hi) ----
        for (int s = 0; s < 16; s++) {
            int slot = tid + s*NTHREADS;           // (mt,ks,lane)
            int smt = slot >> 10, sks = (slot >> 5) & 31, sls = slot & 31;
            int rowa = smt*16 + (sls >> 2);
            int k0 = sks*16 + (sls & 3)*2;
            const float* rp = rsrc + (tok0 + rowa)*D_ + k0;
            float2 v0 = *(const float2*)(rp);
            float2 v1 = *(const float2*)(rp + 8*D_);
            float2 v2 = *(const float2*)(rp + 8);
            float2 v3 = *(const float2*)(rp + 8*D_ + 8);
            *(uint4*)(smem + OFF_AHI + slot*16) =
                make_uint4(pack_hi(v0.x, v0.y), pack_hi(v1.x, v1.y),
                           pack_hi(v2.x, v2.y), pack_hi(v3.x, v3.y));
        }
        if (tid == 0) { *s_nf = 0; *s_np = 0; }
        __syncthreads();

        Top3 t3a, t3b;
        t3_init(t3a); t3_init(t3b);

        for (int ng = 0; ng < 8; ng++) {
            float acc[8][4];
            #pragma unroll
            for (int i = 0; i < 8; i++)
                #pragma unroll
                for (int j = 0; j < 4; j++) acc[i][j] = 0.f;

            for (int hc = 0; hc < 16; hc++) {
                CP_WAIT2();            // this group's half of chunk hcnt resident
                BAR_HALF(1 + nh);      // group-local visibility + slot gate
                if (hcnt + 3 < TOTH)
                    stage_half_h(hcnt+3, sb + OFF_B + ((hcnt+3)&3)*8192, gtid, nh);
                CP_COMMIT();           // uniform per-group count (may be empty)

                const char* bbase = smem + OFF_B + (hcnt&3)*8192 + nh*4096;
                #pragma unroll
                for (int ksl = 0; ksl < 2; ksl++) {
                    int ks = hc*2 + ksl;
                    unsigned aoff = (unsigned)(((mt*32 + ks)*32 + lane)*16);
                    uint4 AH = *(const uint4*)(smem + OFF_AHI + aoff);
                    #pragma unroll
                    for (int pr = 0; pr < 4; pr++) {
                        uint4 Bv = *(const uint4*)(bbase + pr*1024 + ksl*512 + lane*16);
                        mma_f16(acc[pr*2],   AH.x, AH.y, AH.z, AH.w, Bv.x, Bv.y);
                        mma_f16(acc[pr*2+1], AH.x, AH.y, AH.z, AH.w, Bv.z, Bv.w);
                    }
                }
                hcnt++;
            }

            // epilogue: scores for this 64-code group
            int codebase = nh*512 + ng*64;
            #pragma unroll
            for (int ntl = 0; ntl < 8; ntl++) {
                int n0 = codebase + ntl*8 + (lane & 3)*2;
                float cn0 = __ldg(cnq + n0), cn1 = __ldg(cnq + n0 + 1);
                t3_ins(t3a, fmaf(-2.f, acc[ntl][0], cn0), n0);
                t3_ins(t3a, fmaf(-2.f, acc[ntl][1], cn1), n0+1);
                t3_ins(t3b, fmaf(-2.f, acc[ntl][2], cn0), n0);
                t3_ins(t3b, fmaf(-2.f, acc[ntl][3], cn1), n0+1);
            }
        }

        // quad merge (4 lanes share each C row)
        t3_shxor(t3a, 1); t3_shxor(t3a, 2);
        t3_shxor(t3b, 1); t3_shxor(t3b, 2);
        if ((lane & 3) == 0) {
            int r = lane >> 2;
            float* e = s_t3 + ((nh*4 + mt)*16 + r)*6;
            e[0] = t3a.s0; e[1] = t3a.s1; e[2] = t3a.s2;
            ((int*)e)[3] = t3a.i0; ((int*)e)[4] = t3a.i1; ((int*)e)[5] = t3a.i2;
            float* f = s_t3 + ((nh*4 + mt)*16 + r + 8)*6;
            f[0] = t3b.s0; f[1] = t3b.s1; f[2] = t3b.s2;
            ((int*)f)[3] = t3b.i0; ((int*)f)[4] = t3b.i1; ((int*)f)[5] = t3b.i2;
        }
        __syncthreads();

        // merge halves + decide (warps 0-3, lanes 0-15)
        if (nh == 0 && lane < 16) {
            const float* e0 = s_t3 + ((0*4 + mt)*16 + lane)*6;
            const float* e1 = s_t3 + ((1*4 + mt)*16 + lane)*6;
            Top3 t;
            t.s0 = e0[0]; t.s1 = e0[1]; t.s2 = e0[2];
            t.i0 = ((const int*)e0)[3]; t.i1 = ((const int*)e0)[4]; t.i2 = ((const int*)e0)[5];
            t3_ins(t, e1[0], ((const int*)e1)[3]);
            t3_ins(t, e1[1], ((const int*)e1)[4]);
            t3_ins(t, e1[2], ((const int*)e1)[5]);
            int token = mt*16 + lane;
            s_idx[token] = t.i0;
            if (t.s2 - t.s0 < TAU) {
                int p = atomicAdd(s_nf, 1);
                s_flag[p] = token;
            } else if (t.s1 - t.s0 < TAU) {
                int p = atomicAdd(s_np, 1);
                s_pm[p] = token; s_pc[p] = t.i1;
            }
        }
        __syncthreads();

        // ---- pair rescore: exact fp32 compare of top-2 (one warp each) ----
        int np = *s_np;
        for (int p = wid; p < np; p += 8) {
            int m = s_pm[p];
            int ca = s_idx[m], cb2 = s_pc[p];
            const float* rr = rsrc + (tok0 + m)*D_;
            const float* pa = cbq + (size_t)ca*D_;
            const float* pb = cbq + (size_t)cb2*D_;
            float da = 0.f, db = 0.f;
            #pragma unroll
            for (int k = 0; k < 16; k++) {
                float rv = rr[lane*16 + k];
                da = fmaf(rv, pa[lane*16 + k], da);
                db = fmaf(rv, pb[lane*16 + k], db);
            }
            #pragma unroll
            for (int off = 16; off > 0; off >>= 1) {
                da += __shfl_down_sync(0xffffffffu, da, off);
                db += __shfl_down_sync(0xffffffffu, db, off);
            }
            if (lane == 0) {
                float sa = fmaf(-2.f, da, __ldg(cnq + ca));
                float sc = fmaf(-2.f, db, __ldg(cnq + cb2));
                int win = (sc < sa || (sc == sa && cb2 < ca)) ? cb2 : ca;
                s_idx[m] = win;
            }
        }
        __syncthreads();

        // ---- full exact rescore (rare) ----
        int nf = *s_nf;
        for (int f = 0; f < nf; f++) {
            int m = s_flag[f];
            const float* rr = rsrc + (tok0 + m)*D_;
            float lb = FLT_MAX; int li = 0x7fffffff;
            #pragma unroll 1
            for (int jj = 0; jj < 4; jj++) {
                int code = wid*128 + jj*32 + lane;
                const float* cr = cbq + (size_t)code*D_;
                float dot = 0.f;
                #pragma unroll 8
                for (int d = 0; d < D_; d++) dot = fmaf(rr[d], cr[d], dot);
                float sc = fmaf(-2.f, dot, __ldg(cnq + code));
                if (sc < lb || (sc == lb && code < li)) { lb = sc; li = code; }
            }
            #pragma unroll
            for (int off = 16; off > 0; off >>= 1) {
                float os = __shfl_down_sync(0xffffffffu, lb, off);
                int   oi = __shfl_down_sync(0xffffffffu, li, off);
                if (os < lb || (os == lb && oi < li)) { lb = os; li = oi; }
            }
            if (lane == 0) { s_rb[wid] = lb; s_ri[wid] = li; }
            __syncthreads();
            if (tid == 0) {
                float fb = FLT_MAX; int fi = 0x7fffffff;
                #pragma unroll
                for (int wv = 0; wv < 8; wv++)
                    if (s_rb[wv] < fb || (s_rb[wv] == fb && s_ri[wv] < fi)) {
                        fb = s_rb[wv]; fi = s_ri[wv];
                    }
                s_idx[m] = fi;
            }
            __syncthreads();
        }

        // ---- residual update + loss + index output ----
        float lloss = 0.f;
        #pragma unroll 1
        for (int i = 0; i < 8; i++) {
            int m = wid*8 + i;
            int idx = s_idx[m];
            const float* cr = cbq + (size_t)idx*D_;
            const float* rr = rsrc + (tok0 + m)*D_;
            float* wr = g_res + (tok0 + m)*D_;
            #pragma unroll
            for (int it = 0; it < 4; it++) {
                int d = it*128 + lane*4;
                float4 rv = *(const float4*)(rr + d);
                float4 cv = *(const float4*)(cr + d);
                float4 nv = make_float4(rv.x-cv.x, rv.y-cv.y, rv.z-cv.z, rv.w-cv.w);
                *(float4*)(wr + d) = nv;
                lloss = fmaf(nv.x, nv.x, lloss);
                lloss = fmaf(nv.y, nv.y, lloss);
                lloss = fmaf(nv.z, nv.z, lloss);
                lloss = fmaf(nv.w, nv.w, lloss);
            }
            if (lane == 0 && out_size >= (int)((long long)T_*D_ + (long long)T_*Q_))
                out[(size_t)T_*D_ + (tok0 + m)*Q_ + q] = (float)idx;
        }
        #pragma unroll
        for (int off = 16; off > 0; off >>= 1)
            lloss += __shfl_down_sync(0xffffffffu, lloss, off);
        if (lane == 0) s_loss[wid] = lloss;
        __syncthreads();
        if (tid == 0) {
            float s = 0.f;
            #pragma unroll
            for (int i = 0; i < 8; i++) s += s_loss[i];
            g_part[blockIdx.x*Q_ + q] = s;
        }
        __syncthreads();   // residual visible before next q's staging
    }

    // quantized_out = x - residual_final
    for (int i = tid; i < TM*(D_/4); i += NTHREADS) {
        int row = i >> 7, c4 = i & 127;
        float4 xv = ((const float4*)(x + (tok0+row)*D_))[c4];
        float4 rv = ((const float4*)(g_res + (tok0+row)*D_))[c4];
        ((float4*)(out + (tok0+row)*D_))[c4] =
            make_float4(xv.x-rv.x, xv.y-rv.y, xv.z-rv.z, xv.w-rv.w);
    }
}

// ---------------------------------------------------------------------------
__global__ void rvq_fin(float* __restrict__ out, int out_size) {
    int q = threadIdx.x;
    if (q < Q_ && out_size >= (int)((long long)T_*D_ + (long long)T_*Q_ + Q_)) {
        float s = 0.f;
        for (int c = 0; c < NCTA; c++) s += g_part[c*Q_ + q];
        out[(size_t)T_*D_ + (size_t)T_*Q_ + q] = s / (float)((long long)T_*D_);
    }
}

// ---------------------------------------------------------------------------
extern "C" void kernel_launch(void* const* d_in, const int* in_sizes, int n_in,
                              void* d_out, int out_size) {
    const float* x;
    const float* cbs;
    if (in_sizes[0] == T_*D_) { x = (const float*)d_in[0]; cbs = (const float*)d_in[1]; }
    else                      { x = (const float*)d_in[1]; cbs = (const float*)d_in[0]; }
    float* out = (float*)d_out;

    cudaFuncSetAttribute(rvq_main,
                         cudaFuncAttributeMaxDynamicSharedMemorySize, SMEM_BYTES);

    rvq_dummy<<<1, 32>>>();
    rvq_dummy<<<1, 32>>>();
    rvq_dummy<<<1, 32>>>();
    rvq_prep_norm<<<(Q_*C_ + 255)/256, 256>>>(cbs);
    rvq_prep_bfrag2<<<(Q_*64*NKS*32)/256, 256>>>(cbs);
    rvq_main<<<NCTA, NTHREADS, SMEM_BYTES>>>(x, cbs, out, out_size);
    rvq_fin<<<1, 32>>>(out, out_size);
}